// round 2
// baseline (speedup 1.0000x reference)
#include <cuda_runtime.h>
#include <cstdint>

#define BB 2
#define TT 2048
#define DD 768
#define HH 12
#define DH 64
#define BT (BB*TT)

// ---------------- scratch (static device arrays; no allocation) ----------------
__device__ float g_qkv [(size_t)BT * 2304];
__device__ float g_attn[(size_t)BT * DD];
__device__ float g_proj[(size_t)BT * DD];
__device__ float g_n   [(size_t)BT * DD];
__device__ float g_h1  [(size_t)BT * 3072];
__device__ float g_m   [(size_t)BT * DD];

// ---------------- SGEMM: C[M,N] = A[M,K] @ W[K,N] + bias, optional GELU --------
// BM=128 BN=128 BK=16, 256 threads, 8x8 micro-tile per thread.
__global__ __launch_bounds__(256)
void sgemm_bias(const float* __restrict__ A, const float* __restrict__ W,
                const float* __restrict__ bias, float* __restrict__ C,
                int M, int N, int K, int do_gelu)
{
    __shared__ float As[16][128];
    __shared__ float Bs[16][128];

    const int tid = threadIdx.x;
    const int tx = tid & 15;          // 0..15  (cols)
    const int ty = tid >> 4;          // 0..15  (rows)
    const int row0 = blockIdx.y * 128;
    const int col0 = blockIdx.x * 128;

    float acc[8][8];
#pragma unroll
    for (int i = 0; i < 8; i++)
#pragma unroll
        for (int j = 0; j < 8; j++) acc[i][j] = 0.f;

    for (int k0 = 0; k0 < K; k0 += 16) {
        // A tile: 128 rows x 16 cols  -> 512 float4, 2 per thread (transposed store)
#pragma unroll
        for (int l = 0; l < 2; l++) {
            int idx = tid + l * 256;          // 0..511
            int r = idx >> 2;                 // 0..127
            int c = (idx & 3) * 4;            // 0,4,8,12
            float4 v = *reinterpret_cast<const float4*>(&A[(size_t)(row0 + r) * K + k0 + c]);
            As[c + 0][r] = v.x; As[c + 1][r] = v.y;
            As[c + 2][r] = v.z; As[c + 3][r] = v.w;
        }
        // B tile: 16 rows x 128 cols -> 512 float4, 2 per thread
#pragma unroll
        for (int l = 0; l < 2; l++) {
            int idx = tid + l * 256;
            int r = idx >> 5;                 // 0..15
            int c = (idx & 31) * 4;           // 0..124
            float4 v = *reinterpret_cast<const float4*>(&W[(size_t)(k0 + r) * N + col0 + c]);
            *reinterpret_cast<float4*>(&Bs[r][c]) = v;
        }
        __syncthreads();

#pragma unroll
        for (int kk = 0; kk < 16; kk++) {
            float af[8], bf[8];
            float4 a0 = *reinterpret_cast<const float4*>(&As[kk][ty * 8]);
            float4 a1 = *reinterpret_cast<const float4*>(&As[kk][ty * 8 + 4]);
            float4 b0 = *reinterpret_cast<const float4*>(&Bs[kk][tx * 8]);
            float4 b1 = *reinterpret_cast<const float4*>(&Bs[kk][tx * 8 + 4]);
            af[0]=a0.x; af[1]=a0.y; af[2]=a0.z; af[3]=a0.w;
            af[4]=a1.x; af[5]=a1.y; af[6]=a1.z; af[7]=a1.w;
            bf[0]=b0.x; bf[1]=b0.y; bf[2]=b0.z; bf[3]=b0.w;
            bf[4]=b1.x; bf[5]=b1.y; bf[6]=b1.z; bf[7]=b1.w;
#pragma unroll
            for (int i = 0; i < 8; i++)
#pragma unroll
                for (int j = 0; j < 8; j++)
                    acc[i][j] += af[i] * bf[j];
        }
        __syncthreads();
    }

#pragma unroll
    for (int i = 0; i < 8; i++) {
        int row = row0 + ty * 8 + i;
#pragma unroll
        for (int j = 0; j < 8; j++) {
            int col = col0 + tx * 8 + j;
            float v = acc[i][j] + bias[col];
            if (do_gelu) {
                float u = v;
                v = 0.5f * u * (1.0f + tanhf(0.7978845608028654f * (u + 0.044715f * u * u * u)));
            }
            C[(size_t)row * N + col] = v;
        }
    }
}

// ---------------- Flash attention (no scale), ragged key/query mask ------------
// grid: (T/64, H, B), 256 threads. 64 queries x 64 dims per CTA.
__global__ __launch_bounds__(256)
void attn_kernel(const float* __restrict__ qkv, const int* __restrict__ lengths,
                 float* __restrict__ aout)
{
    extern __shared__ float sm[];
    float* Qt = sm;                   // [d][q]  stride 68
    float* Kt = Qt + 64 * 68;         // [d][k]  stride 68
    float* Vs = Kt + 64 * 68;         // [k][d]  stride 68
    float* Pt = Vs + 64 * 68;         // [k][q]  stride 68
    __shared__ float mrow[64], lrow[64], srow[64];

    const int qtile = blockIdx.x;
    const int h = blockIdx.y;
    const int b = blockIdx.z;
    const int len = lengths[b];
    const int tid = threadIdx.x;
    const int tx = tid & 15;
    const int ty = tid >> 4;
    const int t0 = qtile * 64;

    const size_t baseQ = (size_t)b * TT * 2304 + (size_t)h * DH;
    const size_t baseK = baseQ + DD;
    const size_t baseV = baseQ + 2 * DD;

    // load Q tile transposed (d-major)
    for (int i = tid; i < 64 * 64; i += 256) {
        int q = i >> 6, d = i & 63;
        Qt[d * 68 + q] = qkv[baseQ + (size_t)(t0 + q) * 2304 + d];
    }
    if (tid < 64) { mrow[tid] = -1e30f; lrow[tid] = 0.f; }

    float O[4][4];
#pragma unroll
    for (int i = 0; i < 4; i++)
#pragma unroll
        for (int j = 0; j < 4; j++) O[i][j] = 0.f;

    const int ntiles = (len + 63) >> 6;
    for (int kt = 0; kt < ntiles; kt++) {
        const int k0 = kt * 64;
        __syncthreads();   // protect Pt/Kt/Vs from previous iteration & Q/m/l init
        for (int i = tid; i < 64 * 64; i += 256) {
            int k = i >> 6, d = i & 63;
            Kt[d * 68 + k] = qkv[baseK + (size_t)(k0 + k) * 2304 + d];
            Vs[k * 68 + d] = qkv[baseV + (size_t)(k0 + k) * 2304 + d];
        }
        __syncthreads();

        // S = Q @ K^T  (4x4 per thread: q = ty*4+i, k = tx*4+j)
        float sacc[4][4];
#pragma unroll
        for (int i = 0; i < 4; i++)
#pragma unroll
            for (int j = 0; j < 4; j++) sacc[i][j] = 0.f;

        for (int d = 0; d < 64; d++) {
            float4 q4 = *reinterpret_cast<const float4*>(&Qt[d * 68 + ty * 4]);
            float4 k4 = *reinterpret_cast<const float4*>(&Kt[d * 68 + tx * 4]);
            float qa[4] = {q4.x, q4.y, q4.z, q4.w};
            float kb[4] = {k4.x, k4.y, k4.z, k4.w};
#pragma unroll
            for (int i = 0; i < 4; i++)
#pragma unroll
                for (int j = 0; j < 4; j++)
                    sacc[i][j] += qa[i] * kb[j];
        }

        // write (masked) scores to Pt[k][q]
#pragma unroll
        for (int j = 0; j < 4; j++) {
            int kg = k0 + tx * 4 + j;
            bool ok = (kg < len);
#pragma unroll
            for (int i = 0; i < 4; i++)
                Pt[(tx * 4 + j) * 68 + ty * 4 + i] = ok ? sacc[i][j] : -1e30f;
        }
        __syncthreads();

        // online softmax per row (64 threads, one row each)
        if (tid < 64) {
            int q = tid;
            float m_old = mrow[q];
            float mx = m_old;
            for (int k = 0; k < 64; k++) mx = fmaxf(mx, Pt[k * 68 + q]);
            float scale = __expf(m_old - mx);
            float ssum = 0.f;
            for (int k = 0; k < 64; k++) {
                float p = __expf(Pt[k * 68 + q] - mx);
                Pt[k * 68 + q] = p;
                ssum += p;
            }
            lrow[q] = lrow[q] * scale + ssum;
            mrow[q] = mx;
            srow[q] = scale;
        }
        __syncthreads();

        // rescale O, accumulate P @ V
        float sc[4];
#pragma unroll
        for (int i = 0; i < 4; i++) sc[i] = srow[ty * 4 + i];
#pragma unroll
        for (int i = 0; i < 4; i++)
#pragma unroll
            for (int j = 0; j < 4; j++) O[i][j] *= sc[i];

        for (int k = 0; k < 64; k++) {
            float4 p4 = *reinterpret_cast<const float4*>(&Pt[k * 68 + ty * 4]);
            float4 v4 = *reinterpret_cast<const float4*>(&Vs[k * 68 + tx * 4]);
            float pa[4] = {p4.x, p4.y, p4.z, p4.w};
            float vb[4] = {v4.x, v4.y, v4.z, v4.w};
#pragma unroll
            for (int i = 0; i < 4; i++)
#pragma unroll
                for (int j = 0; j < 4; j++)
                    O[i][j] += pa[i] * vb[j];
        }
    }

    // write out: divide by l, zero invalid query rows
#pragma unroll
    for (int i = 0; i < 4; i++) {
        int t = t0 + ty * 4 + i;
        float inv = (t < len) ? (1.f / lrow[ty * 4 + i]) : 0.f;
#pragma unroll
        for (int j = 0; j < 4; j++)
            aout[((size_t)b * TT + t) * DD + h * DH + tx * 4 + j] = O[i][j] * inv;
    }
}

// ---------------- residual + LayerNorm + mask ----------------------------------
__global__ __launch_bounds__(256)
void ln_kernel(const float* __restrict__ a, const float* __restrict__ r,
               const float* __restrict__ g, const float* __restrict__ beta,
               const int* __restrict__ lengths, float* __restrict__ out)
{
    const int row = blockIdx.x;
    const int t = row & (TT - 1);
    const int bi = row >> 11;
    const float maskv = (t < lengths[bi]) ? 1.f : 0.f;
    const float* pa = a + (size_t)row * DD;
    const float* pr = r + (size_t)row * DD;

    float s = 0.f, s2 = 0.f;
    for (int i = threadIdx.x; i < DD; i += 256) {
        float v = pa[i] + pr[i];
        s += v; s2 += v * v;
    }
#pragma unroll
    for (int o = 16; o; o >>= 1) {
        s  += __shfl_down_sync(0xffffffffu, s,  o);
        s2 += __shfl_down_sync(0xffffffffu, s2, o);
    }
    __shared__ float ws[8], ws2[8];
    int w = threadIdx.x >> 5, lane = threadIdx.x & 31;
    if (lane == 0) { ws[w] = s; ws2[w] = s2; }
    __syncthreads();
    if (threadIdx.x == 0) {
        float S = 0.f, S2 = 0.f;
        for (int i = 0; i < 8; i++) { S += ws[i]; S2 += ws2[i]; }
        ws[0] = S; ws2[0] = S2;
    }
    __syncthreads();
    const float mu = ws[0] * (1.f / DD);
    const float var = ws2[0] * (1.f / DD) - mu * mu;
    const float rstd = rsqrtf(var + 1e-5f);
    for (int i = threadIdx.x; i < DD; i += 256) {
        float v = pa[i] + pr[i];
        out[(size_t)row * DD + i] = ((v - mu) * rstd * g[i] + beta[i]) * maskv;
    }
}

// ---------------- launcher ------------------------------------------------------
extern "C" void kernel_launch(void* const* d_in, const int* in_sizes, int n_in,
                              void* d_out, int out_size)
{
    const float* x      = (const float*)d_in[0];
    const int*   lens   = (const int*)  d_in[1];
    const float* w_qkv  = (const float*)d_in[2];
    const float* b_qkv  = (const float*)d_in[3];
    const float* w_proj = (const float*)d_in[4];
    const float* b_proj = (const float*)d_in[5];
    const float* ln1_g  = (const float*)d_in[6];
    const float* ln1_b  = (const float*)d_in[7];
    const float* w_fc   = (const float*)d_in[8];
    const float* b_fc   = (const float*)d_in[9];
    const float* w_out  = (const float*)d_in[10];
    const float* b_out  = (const float*)d_in[11];
    const float* ln2_g  = (const float*)d_in[12];
    const float* ln2_b  = (const float*)d_in[13];
    float* out = (float*)d_out;

    float *p_qkv, *p_attn, *p_proj, *p_n, *p_h1, *p_m;
    cudaGetSymbolAddress((void**)&p_qkv,  g_qkv);
    cudaGetSymbolAddress((void**)&p_attn, g_attn);
    cudaGetSymbolAddress((void**)&p_proj, g_proj);
    cudaGetSymbolAddress((void**)&p_n,    g_n);
    cudaGetSymbolAddress((void**)&p_h1,   g_h1);
    cudaGetSymbolAddress((void**)&p_m,    g_m);

    const int ATTN_SMEM = 4 * 64 * 68 * (int)sizeof(float);   // 69632 B
    cudaFuncSetAttribute(attn_kernel, cudaFuncAttributeMaxDynamicSharedMemorySize, ATTN_SMEM);

    // 1) qkv = x @ w_qkv + b_qkv                [4096, 2304]
    sgemm_bias<<<dim3(2304 / 128, BT / 128), 256>>>(x, w_qkv, b_qkv, p_qkv, BT, 2304, DD, 0);

    // 2) attention                              [4096, 768]
    attn_kernel<<<dim3(TT / 64, HH, BB), 256, ATTN_SMEM>>>(p_qkv, lens, p_attn);

    // 3) proj = attn @ w_proj + b_proj          [4096, 768]
    sgemm_bias<<<dim3(DD / 128, BT / 128), 256>>>(p_attn, w_proj, b_proj, p_proj, BT, DD, DD, 0);

    // 4) n = LN(x + proj) * mask                [4096, 768]
    ln_kernel<<<BT, 256>>>(x, p_proj, ln1_g, ln1_b, lens, p_n);

    // 5) h1 = gelu(n @ w_fc + b_fc)             [4096, 3072]
    sgemm_bias<<<dim3(3072 / 128, BT / 128), 256>>>(p_n, w_fc, b_fc, p_h1, BT, 3072, DD, 1);

    // 6) m = h1 @ w_out + b_out                 [4096, 768]
    sgemm_bias<<<dim3(DD / 128, BT / 128), 256>>>(p_h1, w_out, b_out, p_m, BT, DD, 3072, 0);

    // 7) out = LN(n + m) * mask                 [4096, 768]
    ln_kernel<<<BT, 256>>>(p_n, p_m, ln2_g, ln2_b, lens, out);
}

// round 3
// speedup vs baseline: 1.8021x; 1.8021x over previous
#include <cuda_runtime.h>
#include <cstdint>

#define BB 2
#define TT 2048
#define DD 768
#define HH 12
#define DH 64
#define BT (BB*TT)

// ---------------- scratch (static device arrays; no allocation) ----------------
__device__ float g_qkv [(size_t)BT * 2304];
__device__ float g_attn[(size_t)BT * DD];
__device__ float g_proj[(size_t)BT * DD];
__device__ float g_n   [(size_t)BT * DD];
__device__ float g_h1  [(size_t)BT * 3072];
__device__ float g_m   [(size_t)BT * DD];

__device__ __forceinline__ unsigned f2tf32(float f) {
    unsigned u;
    asm("cvt.rna.tf32.f32 %0, %1;" : "=r"(u) : "f"(f));
    return u;
}

// ---------------- TF32 tensor-core GEMM ----------------------------------------
// C[M,N] = A[M,K] @ W[K,N] + bias, optional GELU.
// BM=128 BN=128 BK=32, 256 threads = 8 warps in 2x4 grid, warp tile 64x32.
// mma.sync.aligned.m16n8k8.row.col.f32.tf32.tf32.f32
#define AS_STRIDE 36
#define BS_STRIDE 136
__global__ __launch_bounds__(256)
void sgemm_tf32(const float* __restrict__ A, const float* __restrict__ W,
                const float* __restrict__ bias, float* __restrict__ C,
                int M, int N, int K, int do_gelu)
{
    __shared__ unsigned As[128][AS_STRIDE];   // [m][k] tf32 bits
    __shared__ unsigned Bs[32][BS_STRIDE];    // [k][n] tf32 bits

    const int tid  = threadIdx.x;
    const int wid  = tid >> 5;
    const int lane = tid & 31;
    const int gid  = lane >> 2;    // 0..7
    const int tig  = lane & 3;     // 0..3
    const int wm   = wid >> 2;     // 0..1 : 64-row slab
    const int wn   = wid & 3;      // 0..3 : 32-col slab
    const int row0 = blockIdx.y * 128;
    const int col0 = blockIdx.x * 128;

    float acc[4][4][4];            // [mt][nt][c0..c3]
#pragma unroll
    for (int mt = 0; mt < 4; mt++)
#pragma unroll
        for (int nt = 0; nt < 4; nt++)
#pragma unroll
            for (int c = 0; c < 4; c++) acc[mt][nt][c] = 0.f;

    for (int k0 = 0; k0 < K; k0 += 32) {
        // ---- A tile: 128x32, 1024 float4, 4 per thread ----
#pragma unroll
        for (int l = 0; l < 4; l++) {
            int idx = tid + l * 256;           // 0..1023
            int r  = idx >> 3;                 // 0..127
            int c  = (idx & 7) * 4;            // 0..28
            float4 v = *reinterpret_cast<const float4*>(&A[(size_t)(row0 + r) * K + k0 + c]);
            As[r][c + 0] = f2tf32(v.x); As[r][c + 1] = f2tf32(v.y);
            As[r][c + 2] = f2tf32(v.z); As[r][c + 3] = f2tf32(v.w);
        }
        // ---- B tile: 32x128, 1024 float4, 4 per thread ----
#pragma unroll
        for (int l = 0; l < 4; l++) {
            int idx = tid + l * 256;
            int r  = idx >> 5;                 // 0..31
            int c  = (idx & 31) * 4;           // 0..124
            float4 v = *reinterpret_cast<const float4*>(&W[(size_t)(k0 + r) * N + col0 + c]);
            Bs[r][c + 0] = f2tf32(v.x); Bs[r][c + 1] = f2tf32(v.y);
            Bs[r][c + 2] = f2tf32(v.z); Bs[r][c + 3] = f2tf32(v.w);
        }
        __syncthreads();

#pragma unroll
        for (int ks = 0; ks < 4; ks++) {
            const int kk = ks * 8;
            unsigned af[4][4];
#pragma unroll
            for (int mt = 0; mt < 4; mt++) {
                int r = wm * 64 + mt * 16 + gid;
                af[mt][0] = As[r    ][kk + tig];
                af[mt][1] = As[r + 8][kk + tig];
                af[mt][2] = As[r    ][kk + tig + 4];
                af[mt][3] = As[r + 8][kk + tig + 4];
            }
            unsigned bf[4][2];
#pragma unroll
            for (int nt = 0; nt < 4; nt++) {
                int n = wn * 32 + nt * 8 + gid;
                bf[nt][0] = Bs[kk + tig    ][n];
                bf[nt][1] = Bs[kk + tig + 4][n];
            }
#pragma unroll
            for (int mt = 0; mt < 4; mt++)
#pragma unroll
                for (int nt = 0; nt < 4; nt++) {
                    asm volatile(
                        "mma.sync.aligned.m16n8k8.row.col.f32.tf32.tf32.f32 "
                        "{%0,%1,%2,%3}, {%4,%5,%6,%7}, {%8,%9}, {%0,%1,%2,%3};"
                        : "+f"(acc[mt][nt][0]), "+f"(acc[mt][nt][1]),
                          "+f"(acc[mt][nt][2]), "+f"(acc[mt][nt][3])
                        : "r"(af[mt][0]), "r"(af[mt][1]), "r"(af[mt][2]), "r"(af[mt][3]),
                          "r"(bf[nt][0]), "r"(bf[nt][1]));
                }
        }
        __syncthreads();
    }

    // ---- epilogue: bias (+gelu), float2 stores ----
#pragma unroll
    for (int mt = 0; mt < 4; mt++) {
#pragma unroll
        for (int nt = 0; nt < 4; nt++) {
            int col = col0 + wn * 32 + nt * 8 + tig * 2;
            float b0 = bias[col], b1 = bias[col + 1];
#pragma unroll
            for (int half = 0; half < 2; half++) {
                int row = row0 + wm * 64 + mt * 16 + gid + half * 8;
                float v0 = acc[mt][nt][half * 2 + 0] + b0;
                float v1 = acc[mt][nt][half * 2 + 1] + b1;
                if (do_gelu) {
                    float u0 = v0, u1 = v1;
                    v0 = 0.5f * u0 * (1.0f + tanhf(0.7978845608028654f * (u0 + 0.044715f * u0 * u0 * u0)));
                    v1 = 0.5f * u1 * (1.0f + tanhf(0.7978845608028654f * (u1 + 0.044715f * u1 * u1 * u1)));
                }
                float2 o = make_float2(v0, v1);
                *reinterpret_cast<float2*>(&C[(size_t)row * N + col]) = o;
            }
        }
    }
}

// ---------------- Flash attention (no scale), ragged key/query mask ------------
// grid: (T/64, H, B), 256 threads. 64 queries x 64 dims per CTA.
__global__ __launch_bounds__(256)
void attn_kernel(const float* __restrict__ qkv, const int* __restrict__ lengths,
                 float* __restrict__ aout)
{
    extern __shared__ float sm[];
    float* Qt = sm;                   // [d][q]  stride 68
    float* Kt = Qt + 64 * 68;         // [d][k]  stride 68
    float* Vs = Kt + 64 * 68;         // [k][d]  stride 68
    float* Pt = Vs + 64 * 68;         // [k][q]  stride 68
    __shared__ float mrow[64], lrow[64], srow[64];

    const int qtile = blockIdx.x;
    const int h = blockIdx.y;
    const int b = blockIdx.z;
    const int len = lengths[b];
    const int tid = threadIdx.x;
    const int tx = tid & 15;
    const int ty = tid >> 4;
    const int t0 = qtile * 64;

    const size_t baseQ = (size_t)b * TT * 2304 + (size_t)h * DH;
    const size_t baseK = baseQ + DD;
    const size_t baseV = baseQ + 2 * DD;

    for (int i = tid; i < 64 * 64; i += 256) {
        int q = i >> 6, d = i & 63;
        Qt[d * 68 + q] = qkv[baseQ + (size_t)(t0 + q) * 2304 + d];
    }
    if (tid < 64) { mrow[tid] = -1e30f; lrow[tid] = 0.f; }

    float O[4][4];
#pragma unroll
    for (int i = 0; i < 4; i++)
#pragma unroll
        for (int j = 0; j < 4; j++) O[i][j] = 0.f;

    const int ntiles = (len + 63) >> 6;
    for (int kt = 0; kt < ntiles; kt++) {
        const int k0 = kt * 64;
        __syncthreads();
        for (int i = tid; i < 64 * 64; i += 256) {
            int k = i >> 6, d = i & 63;
            Kt[d * 68 + k] = qkv[baseK + (size_t)(k0 + k) * 2304 + d];
            Vs[k * 68 + d] = qkv[baseV + (size_t)(k0 + k) * 2304 + d];
        }
        __syncthreads();

        float sacc[4][4];
#pragma unroll
        for (int i = 0; i < 4; i++)
#pragma unroll
            for (int j = 0; j < 4; j++) sacc[i][j] = 0.f;

        for (int d = 0; d < 64; d++) {
            float4 q4 = *reinterpret_cast<const float4*>(&Qt[d * 68 + ty * 4]);
            float4 k4 = *reinterpret_cast<const float4*>(&Kt[d * 68 + tx * 4]);
            float qa[4] = {q4.x, q4.y, q4.z, q4.w};
            float kb[4] = {k4.x, k4.y, k4.z, k4.w};
#pragma unroll
            for (int i = 0; i < 4; i++)
#pragma unroll
                for (int j = 0; j < 4; j++)
                    sacc[i][j] += qa[i] * kb[j];
        }

#pragma unroll
        for (int j = 0; j < 4; j++) {
            int kg = k0 + tx * 4 + j;
            bool ok = (kg < len);
#pragma unroll
            for (int i = 0; i < 4; i++)
                Pt[(tx * 4 + j) * 68 + ty * 4 + i] = ok ? sacc[i][j] : -1e30f;
        }
        __syncthreads();

        if (tid < 64) {
            int q = tid;
            float m_old = mrow[q];
            float mx = m_old;
            for (int k = 0; k < 64; k++) mx = fmaxf(mx, Pt[k * 68 + q]);
            float scale = __expf(m_old - mx);
            float ssum = 0.f;
            for (int k = 0; k < 64; k++) {
                float p = __expf(Pt[k * 68 + q] - mx);
                Pt[k * 68 + q] = p;
                ssum += p;
            }
            lrow[q] = lrow[q] * scale + ssum;
            mrow[q] = mx;
            srow[q] = scale;
        }
        __syncthreads();

        float sc[4];
#pragma unroll
        for (int i = 0; i < 4; i++) sc[i] = srow[ty * 4 + i];
#pragma unroll
        for (int i = 0; i < 4; i++)
#pragma unroll
            for (int j = 0; j < 4; j++) O[i][j] *= sc[i];

        for (int k = 0; k < 64; k++) {
            float4 p4 = *reinterpret_cast<const float4*>(&Pt[k * 68 + ty * 4]);
            float4 v4 = *reinterpret_cast<const float4*>(&Vs[k * 68 + tx * 4]);
            float pa[4] = {p4.x, p4.y, p4.z, p4.w};
            float vb[4] = {v4.x, v4.y, v4.z, v4.w};
#pragma unroll
            for (int i = 0; i < 4; i++)
#pragma unroll
                for (int j = 0; j < 4; j++)
                    O[i][j] += pa[i] * vb[j];
        }
    }

#pragma unroll
    for (int i = 0; i < 4; i++) {
        int t = t0 + ty * 4 + i;
        float inv = (t < len) ? (1.f / lrow[ty * 4 + i]) : 0.f;
#pragma unroll
        for (int j = 0; j < 4; j++)
            aout[((size_t)b * TT + t) * DD + h * DH + tx * 4 + j] = O[i][j] * inv;
    }
}

// ---------------- residual + LayerNorm + mask ----------------------------------
__global__ __launch_bounds__(256)
void ln_kernel(const float* __restrict__ a, const float* __restrict__ r,
               const float* __restrict__ g, const float* __restrict__ beta,
               const int* __restrict__ lengths, float* __restrict__ out)
{
    const int row = blockIdx.x;
    const int t = row & (TT - 1);
    const int bi = row >> 11;
    const float maskv = (t < lengths[bi]) ? 1.f : 0.f;
    const float* pa = a + (size_t)row * DD;
    const float* pr = r + (size_t)row * DD;

    float s = 0.f, s2 = 0.f;
    for (int i = threadIdx.x; i < DD; i += 256) {
        float v = pa[i] + pr[i];
        s += v; s2 += v * v;
    }
#pragma unroll
    for (int o = 16; o; o >>= 1) {
        s  += __shfl_down_sync(0xffffffffu, s,  o);
        s2 += __shfl_down_sync(0xffffffffu, s2, o);
    }
    __shared__ float ws[8], ws2[8];
    int w = threadIdx.x >> 5, lane = threadIdx.x & 31;
    if (lane == 0) { ws[w] = s; ws2[w] = s2; }
    __syncthreads();
    if (threadIdx.x == 0) {
        float S = 0.f, S2 = 0.f;
        for (int i = 0; i < 8; i++) { S += ws[i]; S2 += ws2[i]; }
        ws[0] = S; ws2[0] = S2;
    }
    __syncthreads();
    const float mu = ws[0] * (1.f / DD);
    const float var = ws2[0] * (1.f / DD) - mu * mu;
    const float rstd = rsqrtf(var + 1e-5f);
    for (int i = threadIdx.x; i < DD; i += 256) {
        float v = pa[i] + pr[i];
        out[(size_t)row * DD + i] = ((v - mu) * rstd * g[i] + beta[i]) * maskv;
    }
}

// ---------------- launcher ------------------------------------------------------
extern "C" void kernel_launch(void* const* d_in, const int* in_sizes, int n_in,
                              void* d_out, int out_size)
{
    const float* x      = (const float*)d_in[0];
    const int*   lens   = (const int*)  d_in[1];
    const float* w_qkv  = (const float*)d_in[2];
    const float* b_qkv  = (const float*)d_in[3];
    const float* w_proj = (const float*)d_in[4];
    const float* b_proj = (const float*)d_in[5];
    const float* ln1_g  = (const float*)d_in[6];
    const float* ln1_b  = (const float*)d_in[7];
    const float* w_fc   = (const float*)d_in[8];
    const float* b_fc   = (const float*)d_in[9];
    const float* w_out  = (const float*)d_in[10];
    const float* b_out  = (const float*)d_in[11];
    const float* ln2_g  = (const float*)d_in[12];
    const float* ln2_b  = (const float*)d_in[13];
    float* out = (float*)d_out;

    float *p_qkv, *p_attn, *p_proj, *p_n, *p_h1, *p_m;
    cudaGetSymbolAddress((void**)&p_qkv,  g_qkv);
    cudaGetSymbolAddress((void**)&p_attn, g_attn);
    cudaGetSymbolAddress((void**)&p_proj, g_proj);
    cudaGetSymbolAddress((void**)&p_n,    g_n);
    cudaGetSymbolAddress((void**)&p_h1,   g_h1);
    cudaGetSymbolAddress((void**)&p_m,    g_m);

    const int ATTN_SMEM = 4 * 64 * 68 * (int)sizeof(float);   // 69632 B
    cudaFuncSetAttribute(attn_kernel, cudaFuncAttributeMaxDynamicSharedMemorySize, ATTN_SMEM);

    // 1) qkv = x @ w_qkv + b_qkv                [4096, 2304]
    sgemm_tf32<<<dim3(2304 / 128, BT / 128), 256>>>(x, w_qkv, b_qkv, p_qkv, BT, 2304, DD, 0);

    // 2) attention                              [4096, 768]
    attn_kernel<<<dim3(TT / 64, HH, BB), 256, ATTN_SMEM>>>(p_qkv, lens, p_attn);

    // 3) proj = attn @ w_proj + b_proj          [4096, 768]
    sgemm_tf32<<<dim3(DD / 128, BT / 128), 256>>>(p_attn, w_proj, b_proj, p_proj, BT, DD, DD, 0);

    // 4) n = LN(x + proj) * mask                [4096, 768]
    ln_kernel<<<BT, 256>>>(x, p_proj, ln1_g, ln1_b, lens, p_n);

    // 5) h1 = gelu(n @ w_fc + b_fc)             [4096, 3072]
    sgemm_tf32<<<dim3(3072 / 128, BT / 128), 256>>>(p_n, w_fc, b_fc, p_h1, BT, 3072, DD, 1);

    // 6) m = h1 @ w_out + b_out                 [4096, 768]
    sgemm_tf32<<<dim3(DD / 128, BT / 128), 256>>>(p_h1, w_out, b_out, p_m, BT, DD, 3072, 0);

    // 7) out = LN(n + m) * mask                 [4096, 768]
    ln_kernel<<<BT, 256>>>(p_n, p_m, ln2_g, ln2_b, lens, out);
}

// round 4
// speedup vs baseline: 2.7200x; 1.5093x over previous
#include <cuda_runtime.h>
#include <cstdint>

#define BB 2
#define TT 2048
#define DD 768
#define HH 12
#define DH 64
#define BT (BB*TT)

// ---------------- scratch (static device arrays; no allocation) ----------------
__device__ float g_qkv [(size_t)BT * 2304];
__device__ float g_attn[(size_t)BT * DD];
__device__ float g_proj[(size_t)BT * DD];
__device__ float g_n   [(size_t)BT * DD];
__device__ float g_h1  [(size_t)BT * 3072];
__device__ float g_m   [(size_t)BT * DD];

__device__ __forceinline__ unsigned f2tf32(float f) {
    unsigned u;
    asm("cvt.rna.tf32.f32 %0, %1;" : "=r"(u) : "f"(f));
    return u;
}

__device__ __forceinline__ void mma_tf32(float* c, const unsigned* a, const unsigned* b) {
    asm volatile(
        "mma.sync.aligned.m16n8k8.row.col.f32.tf32.tf32.f32 "
        "{%0,%1,%2,%3}, {%4,%5,%6,%7}, {%8,%9}, {%0,%1,%2,%3};"
        : "+f"(c[0]), "+f"(c[1]), "+f"(c[2]), "+f"(c[3])
        : "r"(a[0]), "r"(a[1]), "r"(a[2]), "r"(a[3]), "r"(b[0]), "r"(b[1]));
}

// ---------------- TF32 tensor-core GEMM ----------------------------------------
// C[M,N] = A[M,K] @ W[K,N] + bias, optional GELU.
// BM=128 BN=128 BK=32, 256 threads = 8 warps in 2x4 grid, warp tile 64x32.
#define AS_STRIDE 36
#define BS_STRIDE 136
__global__ __launch_bounds__(256)
void sgemm_tf32(const float* __restrict__ A, const float* __restrict__ W,
                const float* __restrict__ bias, float* __restrict__ C,
                int M, int N, int K, int do_gelu)
{
    __shared__ unsigned As[128][AS_STRIDE];   // [m][k] tf32 bits
    __shared__ unsigned Bs[32][BS_STRIDE];    // [k][n] tf32 bits

    const int tid  = threadIdx.x;
    const int wid  = tid >> 5;
    const int lane = tid & 31;
    const int gid  = lane >> 2;    // 0..7
    const int tig  = lane & 3;     // 0..3
    const int wm   = wid >> 2;     // 0..1 : 64-row slab
    const int wn   = wid & 3;      // 0..3 : 32-col slab
    const int row0 = blockIdx.y * 128;
    const int col0 = blockIdx.x * 128;

    float acc[4][4][4];
#pragma unroll
    for (int mt = 0; mt < 4; mt++)
#pragma unroll
        for (int nt = 0; nt < 4; nt++)
#pragma unroll
            for (int c = 0; c < 4; c++) acc[mt][nt][c] = 0.f;

    for (int k0 = 0; k0 < K; k0 += 32) {
#pragma unroll
        for (int l = 0; l < 4; l++) {
            int idx = tid + l * 256;
            int r  = idx >> 3;
            int c  = (idx & 7) * 4;
            float4 v = *reinterpret_cast<const float4*>(&A[(size_t)(row0 + r) * K + k0 + c]);
            As[r][c + 0] = f2tf32(v.x); As[r][c + 1] = f2tf32(v.y);
            As[r][c + 2] = f2tf32(v.z); As[r][c + 3] = f2tf32(v.w);
        }
#pragma unroll
        for (int l = 0; l < 4; l++) {
            int idx = tid + l * 256;
            int r  = idx >> 5;
            int c  = (idx & 31) * 4;
            float4 v = *reinterpret_cast<const float4*>(&W[(size_t)(k0 + r) * N + col0 + c]);
            Bs[r][c + 0] = f2tf32(v.x); Bs[r][c + 1] = f2tf32(v.y);
            Bs[r][c + 2] = f2tf32(v.z); Bs[r][c + 3] = f2tf32(v.w);
        }
        __syncthreads();

#pragma unroll
        for (int ks = 0; ks < 4; ks++) {
            const int kk = ks * 8;
            unsigned af[4][4];
#pragma unroll
            for (int mt = 0; mt < 4; mt++) {
                int r = wm * 64 + mt * 16 + gid;
                af[mt][0] = As[r    ][kk + tig];
                af[mt][1] = As[r + 8][kk + tig];
                af[mt][2] = As[r    ][kk + tig + 4];
                af[mt][3] = As[r + 8][kk + tig + 4];
            }
            unsigned bf[4][2];
#pragma unroll
            for (int nt = 0; nt < 4; nt++) {
                int n = wn * 32 + nt * 8 + gid;
                bf[nt][0] = Bs[kk + tig    ][n];
                bf[nt][1] = Bs[kk + tig + 4][n];
            }
#pragma unroll
            for (int mt = 0; mt < 4; mt++)
#pragma unroll
                for (int nt = 0; nt < 4; nt++)
                    mma_tf32(acc[mt][nt], af[mt], bf[nt]);
        }
        __syncthreads();
    }

#pragma unroll
    for (int mt = 0; mt < 4; mt++) {
#pragma unroll
        for (int nt = 0; nt < 4; nt++) {
            int col = col0 + wn * 32 + nt * 8 + tig * 2;
            float b0 = bias[col], b1 = bias[col + 1];
#pragma unroll
            for (int half = 0; half < 2; half++) {
                int row = row0 + wm * 64 + mt * 16 + gid + half * 8;
                float v0 = acc[mt][nt][half * 2 + 0] + b0;
                float v1 = acc[mt][nt][half * 2 + 1] + b1;
                if (do_gelu) {
                    float u0 = v0, u1 = v1;
                    v0 = 0.5f * u0 * (1.0f + tanhf(0.7978845608028654f * (u0 + 0.044715f * u0 * u0 * u0)));
                    v1 = 0.5f * u1 * (1.0f + tanhf(0.7978845608028654f * (u1 + 0.044715f * u1 * u1 * u1)));
                }
                *reinterpret_cast<float2*>(&C[(size_t)row * N + col]) = make_float2(v0, v1);
            }
        }
    }
}

// ---------------- Flash attention, TF32 MMA, ragged mask ------------------------
// grid: (T/64, H, B), 256 threads = 8 warps (4 row-groups x 2 col-groups).
// Tiles 64 queries x 64 keys x 64 dims. All smem strides 68 (conflict-free frags).
__global__ __launch_bounds__(256)
void attn_mma(const float* __restrict__ qkv, const int* __restrict__ lengths,
              float* __restrict__ aout)
{
    __shared__ unsigned Qs[64][68];   // [q][d] tf32
    __shared__ unsigned Ks[64][68];   // [k][d] tf32
    __shared__ unsigned Vs[64][68];   // [k][d] tf32
    __shared__ float    Ss[64][68];   // [q][k] scores / probs
    __shared__ float mrow[64], lrow[64], srow[64];

    const int tid  = threadIdx.x;
    const int wid  = tid >> 5;
    const int lane = tid & 31;
    const int gid  = lane >> 2;
    const int tig  = lane & 3;
    const int wm   = wid & 3;      // 16-row group
    const int wn   = wid >> 2;     // 32-col group

    const int b   = blockIdx.z;
    const int h   = blockIdx.y;
    const int t0  = blockIdx.x * 64;
    const int len = lengths[b];

    const size_t baseQ = (size_t)b * TT * 2304 + (size_t)h * DH;
    const size_t baseK = baseQ + DD;
    const size_t baseV = baseQ + 2 * DD;

    // load Q tile (vectorized, convert to tf32)
#pragma unroll
    for (int l = 0; l < 4; l++) {
        int idx = tid + l * 256;          // 0..1023
        int q  = idx >> 4;                // 0..63
        int d  = (idx & 15) * 4;
        float4 v = *reinterpret_cast<const float4*>(&qkv[baseQ + (size_t)(t0 + q) * 2304 + d]);
        Qs[q][d + 0] = f2tf32(v.x); Qs[q][d + 1] = f2tf32(v.y);
        Qs[q][d + 2] = f2tf32(v.z); Qs[q][d + 3] = f2tf32(v.w);
    }
    if (tid < 64) { mrow[tid] = -1e30f; lrow[tid] = 0.f; }

    float o[4][4];
#pragma unroll
    for (int nt = 0; nt < 4; nt++)
#pragma unroll
        for (int c = 0; c < 4; c++) o[nt][c] = 0.f;

    const int r0 = wm * 16 + gid;
    const int r1 = r0 + 8;
    const int ntiles = (len + 63) >> 6;

    for (int kt = 0; kt < ntiles; kt++) {
        const int k0 = kt * 64;
        __syncthreads();
        // load K and V tiles
#pragma unroll
        for (int l = 0; l < 4; l++) {
            int idx = tid + l * 256;
            int k  = idx >> 4;
            int d  = (idx & 15) * 4;
            size_t off = (size_t)(k0 + k) * 2304 + d;
            float4 kv = *reinterpret_cast<const float4*>(&qkv[baseK + off]);
            float4 vv = *reinterpret_cast<const float4*>(&qkv[baseV + off]);
            Ks[k][d + 0] = f2tf32(kv.x); Ks[k][d + 1] = f2tf32(kv.y);
            Ks[k][d + 2] = f2tf32(kv.z); Ks[k][d + 3] = f2tf32(kv.w);
            Vs[k][d + 0] = f2tf32(vv.x); Vs[k][d + 1] = f2tf32(vv.y);
            Vs[k][d + 2] = f2tf32(vv.z); Vs[k][d + 3] = f2tf32(vv.w);
        }
        __syncthreads();

        // ---- S = Q @ K^T (warp: rows wm*16..+16, cols wn*32..+32) ----
        float s[4][4];
#pragma unroll
        for (int nt = 0; nt < 4; nt++)
#pragma unroll
            for (int c = 0; c < 4; c++) s[nt][c] = 0.f;

#pragma unroll
        for (int ks = 0; ks < 8; ks++) {
            const int kk = ks * 8;
            unsigned af[4];
            af[0] = Qs[r0][kk + tig];
            af[1] = Qs[r1][kk + tig];
            af[2] = Qs[r0][kk + tig + 4];
            af[3] = Qs[r1][kk + tig + 4];
#pragma unroll
            for (int nt = 0; nt < 4; nt++) {
                unsigned bf[2];
                int n = wn * 32 + nt * 8 + gid;
                bf[0] = Ks[n][kk + tig];
                bf[1] = Ks[n][kk + tig + 4];
                mma_tf32(s[nt], af, bf);
            }
        }

        // masked write of S
#pragma unroll
        for (int nt = 0; nt < 4; nt++) {
            int col = wn * 32 + nt * 8 + tig * 2;
            bool ok0 = (k0 + col < len), ok1 = (k0 + col + 1 < len);
            Ss[r0][col    ] = ok0 ? s[nt][0] : -1e30f;
            Ss[r0][col + 1] = ok1 ? s[nt][1] : -1e30f;
            Ss[r1][col    ] = ok0 ? s[nt][2] : -1e30f;
            Ss[r1][col + 1] = ok1 ? s[nt][3] : -1e30f;
        }
        __syncthreads();

        // ---- online softmax: 4 threads per row, 16 keys each ----
        {
            int q = tid >> 2, p = (tid & 3) * 16;
            float mx = -1e30f;
#pragma unroll
            for (int j = 0; j < 16; j++) mx = fmaxf(mx, Ss[q][p + j]);
            mx = fmaxf(mx, __shfl_xor_sync(0xffffffffu, mx, 1));
            mx = fmaxf(mx, __shfl_xor_sync(0xffffffffu, mx, 2));
            float m_old = mrow[q];
            float mnew = fmaxf(m_old, mx);
            float ssum = 0.f;
#pragma unroll
            for (int j = 0; j < 16; j++) {
                float e = __expf(Ss[q][p + j] - mnew);
                Ss[q][p + j] = e;
                ssum += e;
            }
            ssum += __shfl_xor_sync(0xffffffffu, ssum, 1);
            ssum += __shfl_xor_sync(0xffffffffu, ssum, 2);
            if ((tid & 3) == 0) {
                float sc = __expf(m_old - mnew);
                srow[q] = sc;
                lrow[q] = lrow[q] * sc + ssum;
                mrow[q] = mnew;
            }
        }
        __syncthreads();

        // ---- rescale O, accumulate O += P @ V ----
        float sc0 = srow[r0], sc1 = srow[r1];
#pragma unroll
        for (int nt = 0; nt < 4; nt++) {
            o[nt][0] *= sc0; o[nt][1] *= sc0;
            o[nt][2] *= sc1; o[nt][3] *= sc1;
        }
#pragma unroll
        for (int ks = 0; ks < 8; ks++) {
            const int kk = ks * 8;
            unsigned af[4];
            af[0] = f2tf32(Ss[r0][kk + tig]);
            af[1] = f2tf32(Ss[r1][kk + tig]);
            af[2] = f2tf32(Ss[r0][kk + tig + 4]);
            af[3] = f2tf32(Ss[r1][kk + tig + 4]);
#pragma unroll
            for (int nt = 0; nt < 4; nt++) {
                unsigned bf[2];
                int n = wn * 32 + nt * 8 + gid;
                bf[0] = Vs[kk + tig    ][n];
                bf[1] = Vs[kk + tig + 4][n];
                mma_tf32(o[nt], af, bf);
            }
        }
    }

    // ---- epilogue: divide by l, zero invalid queries ----
    const int tq0 = t0 + r0, tq1 = t0 + r1;
    const float inv0 = (tq0 < len) ? (1.f / lrow[r0]) : 0.f;
    const float inv1 = (tq1 < len) ? (1.f / lrow[r1]) : 0.f;
#pragma unroll
    for (int nt = 0; nt < 4; nt++) {
        int col = h * DH + wn * 32 + nt * 8 + tig * 2;
        *reinterpret_cast<float2*>(&aout[((size_t)b * TT + tq0) * DD + col]) =
            make_float2(o[nt][0] * inv0, o[nt][1] * inv0);
        *reinterpret_cast<float2*>(&aout[((size_t)b * TT + tq1) * DD + col]) =
            make_float2(o[nt][2] * inv1, o[nt][3] * inv1);
    }
}

// ---------------- residual + LayerNorm + mask ----------------------------------
__global__ __launch_bounds__(256)
void ln_kernel(const float* __restrict__ a, const float* __restrict__ r,
               const float* __restrict__ g, const float* __restrict__ beta,
               const int* __restrict__ lengths, float* __restrict__ out)
{
    const int row = blockIdx.x;
    const int t = row & (TT - 1);
    const int bi = row >> 11;
    const float maskv = (t < lengths[bi]) ? 1.f : 0.f;
    const float* pa = a + (size_t)row * DD;
    const float* pr = r + (size_t)row * DD;

    float s = 0.f, s2 = 0.f;
    for (int i = threadIdx.x; i < DD; i += 256) {
        float v = pa[i] + pr[i];
        s += v; s2 += v * v;
    }
#pragma unroll
    for (int o = 16; o; o >>= 1) {
        s  += __shfl_down_sync(0xffffffffu, s,  o);
        s2 += __shfl_down_sync(0xffffffffu, s2, o);
    }
    __shared__ float ws[8], ws2[8];
    int w = threadIdx.x >> 5, lane = threadIdx.x & 31;
    if (lane == 0) { ws[w] = s; ws2[w] = s2; }
    __syncthreads();
    if (threadIdx.x == 0) {
        float S = 0.f, S2 = 0.f;
        for (int i = 0; i < 8; i++) { S += ws[i]; S2 += ws2[i]; }
        ws[0] = S; ws2[0] = S2;
    }
    __syncthreads();
    const float mu = ws[0] * (1.f / DD);
    const float var = ws2[0] * (1.f / DD) - mu * mu;
    const float rstd = rsqrtf(var + 1e-5f);
    for (int i = threadIdx.x; i < DD; i += 256) {
        float v = pa[i] + pr[i];
        out[(size_t)row * DD + i] = ((v - mu) * rstd * g[i] + beta[i]) * maskv;
    }
}

// ---------------- launcher ------------------------------------------------------
extern "C" void kernel_launch(void* const* d_in, const int* in_sizes, int n_in,
                              void* d_out, int out_size)
{
    const float* x      = (const float*)d_in[0];
    const int*   lens   = (const int*)  d_in[1];
    const float* w_qkv  = (const float*)d_in[2];
    const float* b_qkv  = (const float*)d_in[3];
    const float* w_proj = (const float*)d_in[4];
    const float* b_proj = (const float*)d_in[5];
    const float* ln1_g  = (const float*)d_in[6];
    const float* ln1_b  = (const float*)d_in[7];
    const float* w_fc   = (const float*)d_in[8];
    const float* b_fc   = (const float*)d_in[9];
    const float* w_out  = (const float*)d_in[10];
    const float* b_out  = (const float*)d_in[11];
    const float* ln2_g  = (const float*)d_in[12];
    const float* ln2_b  = (const float*)d_in[13];
    float* out = (float*)d_out;

    float *p_qkv, *p_attn, *p_proj, *p_n, *p_h1, *p_m;
    cudaGetSymbolAddress((void**)&p_qkv,  g_qkv);
    cudaGetSymbolAddress((void**)&p_attn, g_attn);
    cudaGetSymbolAddress((void**)&p_proj, g_proj);
    cudaGetSymbolAddress((void**)&p_n,    g_n);
    cudaGetSymbolAddress((void**)&p_h1,   g_h1);
    cudaGetSymbolAddress((void**)&p_m,    g_m);

    // 1) qkv = x @ w_qkv + b_qkv                [4096, 2304]
    sgemm_tf32<<<dim3(2304 / 128, BT / 128), 256>>>(x, w_qkv, b_qkv, p_qkv, BT, 2304, DD, 0);

    // 2) attention                              [4096, 768]
    attn_mma<<<dim3(TT / 64, HH, BB), 256>>>(p_qkv, lens, p_attn);

    // 3) proj = attn @ w_proj + b_proj          [4096, 768]
    sgemm_tf32<<<dim3(DD / 128, BT / 128), 256>>>(p_attn, w_proj, b_proj, p_proj, BT, DD, DD, 0);

    // 4) n = LN(x + proj) * mask                [4096, 768]
    ln_kernel<<<BT, 256>>>(x, p_proj, ln1_g, ln1_b, lens, p_n);

    // 5) h1 = gelu(n @ w_fc + b_fc)             [4096, 3072]
    sgemm_tf32<<<dim3(3072 / 128, BT / 128), 256>>>(p_n, w_fc, b_fc, p_h1, BT, 3072, DD, 1);

    // 6) m = h1 @ w_out + b_out                 [4096, 768]
    sgemm_tf32<<<dim3(DD / 128, BT / 128), 256>>>(p_h1, w_out, b_out, p_m, BT, DD, 3072, 0);

    // 7) out = LN(n + m) * mask                 [4096, 768]
    ln_kernel<<<BT, 256>>>(p_n, p_m, ln2_g, ln2_b, lens, out);
}

// round 5
// speedup vs baseline: 2.9067x; 1.0686x over previous
#include <cuda_runtime.h>
#include <cstdint>

#define BB 2
#define TT 2048
#define DD 768
#define HH 12
#define DH 64
#define BT (BB*TT)

// ---------------- scratch (static device arrays; no allocation) ----------------
__device__ float g_qkv [(size_t)BT * 2304];
__device__ float g_attn[(size_t)BT * DD];
__device__ float g_proj[(size_t)BT * DD];
__device__ float g_n   [(size_t)BT * DD];
__device__ float g_h1  [(size_t)BT * 3072];
__device__ float g_m   [(size_t)BT * DD];

__device__ __forceinline__ unsigned f2tf32(float f) {
    unsigned u;
    asm("cvt.rna.tf32.f32 %0, %1;" : "=r"(u) : "f"(f));
    return u;
}

__device__ __forceinline__ void mma_tf32(float* c, const unsigned* a, const unsigned* b) {
    asm volatile(
        "mma.sync.aligned.m16n8k8.row.col.f32.tf32.tf32.f32 "
        "{%0,%1,%2,%3}, {%4,%5,%6,%7}, {%8,%9}, {%0,%1,%2,%3};"
        : "+f"(c[0]), "+f"(c[1]), "+f"(c[2]), "+f"(c[3])
        : "r"(a[0]), "r"(a[1]), "r"(a[2]), "r"(a[3]), "r"(b[0]), "r"(b[1]));
}

// ---------------- TF32 tensor-core GEMM, cp.async double-buffered ---------------
// C[M,N] = A[M,K] @ W[K,N] + bias, optional GELU.
// BM=128 BN=128 BK=32, 256 threads = 8 warps (2x4), warp tile 64x32.
// Raw fp32 bits staged in smem; round-to-nearest tf32 via +0x1000 at frag load.
#define A_STRIDE 36
#define B_STRIDE 136
#define A_SZ (128 * A_STRIDE)
#define B_SZ (32 * B_STRIDE)
#define STG_SZ (A_SZ + B_SZ)
#define GEMM_SMEM (2 * STG_SZ * 4)

__global__ __launch_bounds__(256)
void sgemm_tf32(const float* __restrict__ A, const float* __restrict__ W,
                const float* __restrict__ bias, float* __restrict__ C,
                int M, int N, int K, int do_gelu)
{
    extern __shared__ unsigned sm[];

    const int tid  = threadIdx.x;
    const int wid  = tid >> 5;
    const int lane = tid & 31;
    const int gid  = lane >> 2;    // 0..7
    const int tig  = lane & 3;     // 0..3
    const int wm   = wid >> 2;     // 0..1 : 64-row slab
    const int wn   = wid & 3;      // 0..3 : 32-col slab
    const int row0 = blockIdx.y * 128;
    const int col0 = blockIdx.x * 128;

    // per-thread cp.async coordinates
    const int ar = tid >> 3;            // A row 0..31 base (+32*l)
    const int ac = (tid & 7) * 4;       // A col
    const int br = tid >> 5;            // B row 0..7 base (+8*l)
    const int bc = (tid & 31) * 4;      // B col

    float acc[4][4][4];
#pragma unroll
    for (int mt = 0; mt < 4; mt++)
#pragma unroll
        for (int nt = 0; nt < 4; nt++)
#pragma unroll
            for (int c = 0; c < 4; c++) acc[mt][nt][c] = 0.f;

    const int KT = K >> 5;

    // ---- stage loader ----
    auto ld_stage = [&](int s, int k0) {
        unsigned* As = sm + s * STG_SZ;
        unsigned* Bs = sm + s * STG_SZ + A_SZ;
#pragma unroll
        for (int l = 0; l < 4; l++) {
            int r = ar + l * 32;
            unsigned dst = (unsigned)__cvta_generic_to_shared(&As[r * A_STRIDE + ac]);
            const float* src = &A[(size_t)(row0 + r) * K + k0 + ac];
            asm volatile("cp.async.cg.shared.global [%0], [%1], 16;\n" :: "r"(dst), "l"(src));
        }
#pragma unroll
        for (int l = 0; l < 4; l++) {
            int r = br + l * 8;
            unsigned dst = (unsigned)__cvta_generic_to_shared(&Bs[r * B_STRIDE + bc]);
            const float* src = &W[(size_t)(k0 + r) * N + col0 + bc];
            asm volatile("cp.async.cg.shared.global [%0], [%1], 16;\n" :: "r"(dst), "l"(src));
        }
    };

    ld_stage(0, 0);
    asm volatile("cp.async.commit_group;\n" ::);

    for (int kt = 0; kt < KT; kt++) {
        if (kt + 1 < KT) ld_stage((kt + 1) & 1, (kt + 1) * 32);
        asm volatile("cp.async.commit_group;\n" ::);
        asm volatile("cp.async.wait_group 1;\n" ::);
        __syncthreads();

        const unsigned* As = sm + (kt & 1) * STG_SZ;
        const unsigned* Bs = sm + (kt & 1) * STG_SZ + A_SZ;

#pragma unroll
        for (int ks = 0; ks < 4; ks++) {
            const int kk = ks * 8;
            unsigned af[4][4];
#pragma unroll
            for (int mt = 0; mt < 4; mt++) {
                int r = wm * 64 + mt * 16 + gid;
                af[mt][0] = As[ r      * A_STRIDE + kk + tig    ] + 0x1000u;
                af[mt][1] = As[(r + 8) * A_STRIDE + kk + tig    ] + 0x1000u;
                af[mt][2] = As[ r      * A_STRIDE + kk + tig + 4] + 0x1000u;
                af[mt][3] = As[(r + 8) * A_STRIDE + kk + tig + 4] + 0x1000u;
            }
            unsigned bf[4][2];
#pragma unroll
            for (int nt = 0; nt < 4; nt++) {
                int n = wn * 32 + nt * 8 + gid;
                bf[nt][0] = Bs[(kk + tig    ) * B_STRIDE + n] + 0x1000u;
                bf[nt][1] = Bs[(kk + tig + 4) * B_STRIDE + n] + 0x1000u;
            }
#pragma unroll
            for (int mt = 0; mt < 4; mt++)
#pragma unroll
                for (int nt = 0; nt < 4; nt++)
                    mma_tf32(acc[mt][nt], af[mt], bf[nt]);
        }
        __syncthreads();
    }

    // ---- epilogue: bias (+gelu), float2 stores ----
#pragma unroll
    for (int mt = 0; mt < 4; mt++) {
#pragma unroll
        for (int nt = 0; nt < 4; nt++) {
            int col = col0 + wn * 32 + nt * 8 + tig * 2;
            float b0 = bias[col], b1 = bias[col + 1];
#pragma unroll
            for (int half = 0; half < 2; half++) {
                int row = row0 + wm * 64 + mt * 16 + gid + half * 8;
                float v0 = acc[mt][nt][half * 2 + 0] + b0;
                float v1 = acc[mt][nt][half * 2 + 1] + b1;
                if (do_gelu) {
                    float u0 = v0, u1 = v1;
                    v0 = 0.5f * u0 * (1.0f + tanhf(0.7978845608028654f * (u0 + 0.044715f * u0 * u0 * u0)));
                    v1 = 0.5f * u1 * (1.0f + tanhf(0.7978845608028654f * (u1 + 0.044715f * u1 * u1 * u1)));
                }
                *reinterpret_cast<float2*>(&C[(size_t)row * N + col]) = make_float2(v0, v1);
            }
        }
    }
}

// ---------------- Flash attention, TF32 MMA, ragged mask ------------------------
// grid: (T/64, H, B), 256 threads = 8 warps (4 row-groups x 2 col-groups).
__global__ __launch_bounds__(256)
void attn_mma(const float* __restrict__ qkv, const int* __restrict__ lengths,
              float* __restrict__ aout)
{
    __shared__ unsigned Qs[64][68];   // [q][d] tf32
    __shared__ unsigned Ks[64][68];   // [k][d] tf32
    __shared__ unsigned Vs[64][68];   // [k][d] tf32
    __shared__ float    Ss[64][68];   // [q][k] scores / probs
    __shared__ float mrow[64], lrow[64], srow[64];

    const int tid  = threadIdx.x;
    const int wid  = tid >> 5;
    const int lane = tid & 31;
    const int gid  = lane >> 2;
    const int tig  = lane & 3;
    const int wm   = wid & 3;      // 16-row group
    const int wn   = wid >> 2;     // 32-col group

    const int b   = blockIdx.z;
    const int h   = blockIdx.y;
    const int t0  = blockIdx.x * 64;
    const int len = lengths[b];

    const size_t baseQ = (size_t)b * TT * 2304 + (size_t)h * DH;
    const size_t baseK = baseQ + DD;
    const size_t baseV = baseQ + 2 * DD;

#pragma unroll
    for (int l = 0; l < 4; l++) {
        int idx = tid + l * 256;
        int q  = idx >> 4;
        int d  = (idx & 15) * 4;
        float4 v = *reinterpret_cast<const float4*>(&qkv[baseQ + (size_t)(t0 + q) * 2304 + d]);
        Qs[q][d + 0] = f2tf32(v.x); Qs[q][d + 1] = f2tf32(v.y);
        Qs[q][d + 2] = f2tf32(v.z); Qs[q][d + 3] = f2tf32(v.w);
    }
    if (tid < 64) { mrow[tid] = -1e30f; lrow[tid] = 0.f; }

    float o[4][4];
#pragma unroll
    for (int nt = 0; nt < 4; nt++)
#pragma unroll
        for (int c = 0; c < 4; c++) o[nt][c] = 0.f;

    const int r0 = wm * 16 + gid;
    const int r1 = r0 + 8;
    const int ntiles = (len + 63) >> 6;

    for (int kt = 0; kt < ntiles; kt++) {
        const int k0 = kt * 64;
        __syncthreads();
#pragma unroll
        for (int l = 0; l < 4; l++) {
            int idx = tid + l * 256;
            int k  = idx >> 4;
            int d  = (idx & 15) * 4;
            size_t off = (size_t)(k0 + k) * 2304 + d;
            float4 kv = *reinterpret_cast<const float4*>(&qkv[baseK + off]);
            float4 vv = *reinterpret_cast<const float4*>(&qkv[baseV + off]);
            Ks[k][d + 0] = f2tf32(kv.x); Ks[k][d + 1] = f2tf32(kv.y);
            Ks[k][d + 2] = f2tf32(kv.z); Ks[k][d + 3] = f2tf32(kv.w);
            Vs[k][d + 0] = f2tf32(vv.x); Vs[k][d + 1] = f2tf32(vv.y);
            Vs[k][d + 2] = f2tf32(vv.z); Vs[k][d + 3] = f2tf32(vv.w);
        }
        __syncthreads();

        float s[4][4];
#pragma unroll
        for (int nt = 0; nt < 4; nt++)
#pragma unroll
            for (int c = 0; c < 4; c++) s[nt][c] = 0.f;

#pragma unroll
        for (int ks = 0; ks < 8; ks++) {
            const int kk = ks * 8;
            unsigned af[4];
            af[0] = Qs[r0][kk + tig];
            af[1] = Qs[r1][kk + tig];
            af[2] = Qs[r0][kk + tig + 4];
            af[3] = Qs[r1][kk + tig + 4];
#pragma unroll
            for (int nt = 0; nt < 4; nt++) {
                unsigned bf[2];
                int n = wn * 32 + nt * 8 + gid;
                bf[0] = Ks[n][kk + tig];
                bf[1] = Ks[n][kk + tig + 4];
                mma_tf32(s[nt], af, bf);
            }
        }

#pragma unroll
        for (int nt = 0; nt < 4; nt++) {
            int col = wn * 32 + nt * 8 + tig * 2;
            bool ok0 = (k0 + col < len), ok1 = (k0 + col + 1 < len);
            Ss[r0][col    ] = ok0 ? s[nt][0] : -1e30f;
            Ss[r0][col + 1] = ok1 ? s[nt][1] : -1e30f;
            Ss[r1][col    ] = ok0 ? s[nt][2] : -1e30f;
            Ss[r1][col + 1] = ok1 ? s[nt][3] : -1e30f;
        }
        __syncthreads();

        {
            int q = tid >> 2, p = (tid & 3) * 16;
            float mx = -1e30f;
#pragma unroll
            for (int j = 0; j < 16; j++) mx = fmaxf(mx, Ss[q][p + j]);
            mx = fmaxf(mx, __shfl_xor_sync(0xffffffffu, mx, 1));
            mx = fmaxf(mx, __shfl_xor_sync(0xffffffffu, mx, 2));
            float m_old = mrow[q];
            float mnew = fmaxf(m_old, mx);
            float ssum = 0.f;
#pragma unroll
            for (int j = 0; j < 16; j++) {
                float e = __expf(Ss[q][p + j] - mnew);
                Ss[q][p + j] = e;
                ssum += e;
            }
            ssum += __shfl_xor_sync(0xffffffffu, ssum, 1);
            ssum += __shfl_xor_sync(0xffffffffu, ssum, 2);
            if ((tid & 3) == 0) {
                float sc = __expf(m_old - mnew);
                srow[q] = sc;
                lrow[q] = lrow[q] * sc + ssum;
                mrow[q] = mnew;
            }
        }
        __syncthreads();

        float sc0 = srow[r0], sc1 = srow[r1];
#pragma unroll
        for (int nt = 0; nt < 4; nt++) {
            o[nt][0] *= sc0; o[nt][1] *= sc0;
            o[nt][2] *= sc1; o[nt][3] *= sc1;
        }
#pragma unroll
        for (int ks = 0; ks < 8; ks++) {
            const int kk = ks * 8;
            unsigned af[4];
            af[0] = f2tf32(Ss[r0][kk + tig]);
            af[1] = f2tf32(Ss[r1][kk + tig]);
            af[2] = f2tf32(Ss[r0][kk + tig + 4]);
            af[3] = f2tf32(Ss[r1][kk + tig + 4]);
#pragma unroll
            for (int nt = 0; nt < 4; nt++) {
                unsigned bf[2];
                int n = wn * 32 + nt * 8 + gid;
                bf[0] = Vs[kk + tig    ][n];
                bf[1] = Vs[kk + tig + 4][n];
                mma_tf32(o[nt], af, bf);
            }
        }
    }

    const int tq0 = t0 + r0, tq1 = t0 + r1;
    const float inv0 = (tq0 < len) ? (1.f / lrow[r0]) : 0.f;
    const float inv1 = (tq1 < len) ? (1.f / lrow[r1]) : 0.f;
#pragma unroll
    for (int nt = 0; nt < 4; nt++) {
        int col = h * DH + wn * 32 + nt * 8 + tig * 2;
        *reinterpret_cast<float2*>(&aout[((size_t)b * TT + tq0) * DD + col]) =
            make_float2(o[nt][0] * inv0, o[nt][1] * inv0);
        *reinterpret_cast<float2*>(&aout[((size_t)b * TT + tq1) * DD + col]) =
            make_float2(o[nt][2] * inv1, o[nt][3] * inv1);
    }
}

// ---------------- residual + LayerNorm + mask ----------------------------------
__global__ __launch_bounds__(256)
void ln_kernel(const float* __restrict__ a, const float* __restrict__ r,
               const float* __restrict__ g, const float* __restrict__ beta,
               const int* __restrict__ lengths, float* __restrict__ out)
{
    const int row = blockIdx.x;
    const int t = row & (TT - 1);
    const int bi = row >> 11;
    const float maskv = (t < lengths[bi]) ? 1.f : 0.f;
    const float* pa = a + (size_t)row * DD;
    const float* pr = r + (size_t)row * DD;

    float s = 0.f, s2 = 0.f;
    for (int i = threadIdx.x; i < DD; i += 256) {
        float v = pa[i] + pr[i];
        s += v; s2 += v * v;
    }
#pragma unroll
    for (int o = 16; o; o >>= 1) {
        s  += __shfl_down_sync(0xffffffffu, s,  o);
        s2 += __shfl_down_sync(0xffffffffu, s2, o);
    }
    __shared__ float ws[8], ws2[8];
    int w = threadIdx.x >> 5, lane = threadIdx.x & 31;
    if (lane == 0) { ws[w] = s; ws2[w] = s2; }
    __syncthreads();
    if (threadIdx.x == 0) {
        float S = 0.f, S2 = 0.f;
        for (int i = 0; i < 8; i++) { S += ws[i]; S2 += ws2[i]; }
        ws[0] = S; ws2[0] = S2;
    }
    __syncthreads();
    const float mu = ws[0] * (1.f / DD);
    const float var = ws2[0] * (1.f / DD) - mu * mu;
    const float rstd = rsqrtf(var + 1e-5f);
    for (int i = threadIdx.x; i < DD; i += 256) {
        float v = pa[i] + pr[i];
        out[(size_t)row * DD + i] = ((v - mu) * rstd * g[i] + beta[i]) * maskv;
    }
}

// ---------------- launcher ------------------------------------------------------
extern "C" void kernel_launch(void* const* d_in, const int* in_sizes, int n_in,
                              void* d_out, int out_size)
{
    const float* x      = (const float*)d_in[0];
    const int*   lens   = (const int*)  d_in[1];
    const float* w_qkv  = (const float*)d_in[2];
    const float* b_qkv  = (const float*)d_in[3];
    const float* w_proj = (const float*)d_in[4];
    const float* b_proj = (const float*)d_in[5];
    const float* ln1_g  = (const float*)d_in[6];
    const float* ln1_b  = (const float*)d_in[7];
    const float* w_fc   = (const float*)d_in[8];
    const float* b_fc   = (const float*)d_in[9];
    const float* w_out  = (const float*)d_in[10];
    const float* b_out  = (const float*)d_in[11];
    const float* ln2_g  = (const float*)d_in[12];
    const float* ln2_b  = (const float*)d_in[13];
    float* out = (float*)d_out;

    float *p_qkv, *p_attn, *p_proj, *p_n, *p_h1, *p_m;
    cudaGetSymbolAddress((void**)&p_qkv,  g_qkv);
    cudaGetSymbolAddress((void**)&p_attn, g_attn);
    cudaGetSymbolAddress((void**)&p_proj, g_proj);
    cudaGetSymbolAddress((void**)&p_n,    g_n);
    cudaGetSymbolAddress((void**)&p_h1,   g_h1);
    cudaGetSymbolAddress((void**)&p_m,    g_m);

    cudaFuncSetAttribute(sgemm_tf32, cudaFuncAttributeMaxDynamicSharedMemorySize, GEMM_SMEM);

    // 1) qkv = x @ w_qkv + b_qkv                [4096, 2304]
    sgemm_tf32<<<dim3(2304 / 128, BT / 128), 256, GEMM_SMEM>>>(x, w_qkv, b_qkv, p_qkv, BT, 2304, DD, 0);

    // 2) attention                              [4096, 768]
    attn_mma<<<dim3(TT / 64, HH, BB), 256>>>(p_qkv, lens, p_attn);

    // 3) proj = attn @ w_proj + b_proj          [4096, 768]
    sgemm_tf32<<<dim3(DD / 128, BT / 128), 256, GEMM_SMEM>>>(p_attn, w_proj, b_proj, p_proj, BT, DD, DD, 0);

    // 4) n = LN(x + proj) * mask                [4096, 768]
    ln_kernel<<<BT, 256>>>(x, p_proj, ln1_g, ln1_b, lens, p_n);

    // 5) h1 = gelu(n @ w_fc + b_fc)             [4096, 3072]
    sgemm_tf32<<<dim3(3072 / 128, BT / 128), 256, GEMM_SMEM>>>(p_n, w_fc, b_fc, p_h1, BT, 3072, DD, 1);

    // 6) m = h1 @ w_out + b_out                 [4096, 768]
    sgemm_tf32<<<dim3(DD / 128, BT / 128), 256, GEMM_SMEM>>>(p_h1, w_out, b_out, p_m, BT, DD, 3072, 0);

    // 7) out = LN(n + m) * mask                 [4096, 768]
    ln_kernel<<<BT, 256>>>(p_n, p_m, ln2_g, ln2_b, lens, out);
}